// round 1
// baseline (speedup 1.0000x reference)
#include <cuda_runtime.h>
#include <cstdint>
#include <math_constants.h>

#define ENC_DIM 512
#define DEC_DIM 1024
#define HID     128
#define BB      64
#define TT      2048

// ---------------- scratch (no cudaMalloc allowed) ----------------
__device__ float g_q[BB * HID];
__device__ float g_scores[BB * TT];
__device__ float g_ctx_part[8][BB][ENC_DIM];
__device__ int   g_mask_u8;

// ---------------- kernel 0: detect mask dtype ----------------
// mask is logically bool [B,T]. It may be stored as uint8 (1 byte/elem) or
// int32 (4 bytes/elem, values 0/1). Read the first B*T bytes (in-bounds under
// BOTH layouts) as u32 words: if storage is int32, every word is 0 or 1.
// If storage is uint8, words pack 4 bools -> some word > 1 with prob ~1.
__global__ void detect_mask_kernel(const uint4* __restrict__ m) {
    __shared__ int s;
    if (threadIdx.x == 0) s = 0;
    __syncthreads();
    int found = 0;
    const int n16 = (BB * TT) / 16;  // 8192 uint4 covering B*T bytes
    for (int i = threadIdx.x; i < n16; i += blockDim.x) {
        uint4 v = m[i];
        found |= (v.x > 1u) | (v.y > 1u) | (v.z > 1u) | (v.w > 1u);
    }
    if (found) atomicOr(&s, 1);
    __syncthreads();
    if (threadIdx.x == 0) g_mask_u8 = s;
}

// ---------------- kernel 1: q = decoder_state @ W_w^T  [B, HID] ----------------
__global__ void q_kernel(const float* __restrict__ dec, const float* __restrict__ Ww) {
    __shared__ float sdec[DEC_DIM];
    int b = blockIdx.x;
    for (int i = threadIdx.x; i < DEC_DIM; i += blockDim.x)
        sdec[i] = dec[b * DEC_DIM + i];
    __syncthreads();
    int h = threadIdx.x;  // 128 threads
    const float4* wr = (const float4*)(Ww + (size_t)h * DEC_DIM);
    const float4* dr = (const float4*)sdec;
    float acc = 0.f;
#pragma unroll 8
    for (int i = 0; i < DEC_DIM / 4; i++) {
        float4 w4 = wr[i];
        float4 d4 = dr[i];
        acc += w4.x * d4.x + w4.y * d4.y + w4.z * d4.z + w4.w * d4.w;
    }
    g_q[b * HID + h] = acc;
}

// ---------------- kernel 2: scores (the big GEMM + tanh epilogue) ----------------
// Tile: 128 tokens x 128 hid, K-chunks of 32. 256 threads = 16x16, each thread
// owns 8 rows (contiguous) x 8 cols (stride-16). Accumulation uses packed
// fma.rn.f32x2: each 64-bit acc holds (even-k partial, odd-k partial), pairs of
// adjacent k loaded directly as LDS.64 from smem (pitch 34 keeps 8B alignment
// and makes the strided-column B reads conflict-free).
#define KC    32
#define PITCH 34

__global__ __launch_bounds__(256, 1) void scores_kernel(
    const float* __restrict__ enc, const float* __restrict__ Vw,
    const float* __restrict__ Vb, const float* __restrict__ ww,
    const float* __restrict__ wb)
{
    __shared__ float As[128 * PITCH];
    __shared__ float Bs[128 * PITCH];
    __shared__ float sVb[HID], sq[HID], sw[HID];

    int bidx = blockIdx.x;         // 0..1023
    int b    = bidx >> 4;          // batch
    int t0   = (bidx & 15) << 7;   // token tile start

    int tid = threadIdx.x;
    int tx  = tid & 15;
    int ty  = tid >> 4;

    if (tid < HID) {
        sVb[tid] = Vb[tid];
        sq[tid]  = g_q[b * HID + tid];
        sw[tid]  = ww[tid];
    }

    const float* Ag = enc + ((size_t)(b * TT + t0)) * ENC_DIM;

    unsigned long long acc[8][8];
#pragma unroll
    for (int i = 0; i < 8; i++)
#pragma unroll
        for (int j = 0; j < 8; j++) acc[i][j] = 0ull;

    for (int kc = 0; kc < ENC_DIM; kc += KC) {
        __syncthreads();  // previous chunk fully consumed
        // load A tile: 128 rows x 32 cols (8 float4 per row), coalesced
#pragma unroll
        for (int i = 0; i < 4; i++) {
            int idx = tid + i * 256;       // 0..1023
            int row = idx >> 3;
            int k4  = (idx & 7) << 2;
            float4 v = *(const float4*)(Ag + (size_t)row * ENC_DIM + kc + k4);
            float* dst = &As[row * PITCH + k4];
            dst[0] = v.x; dst[1] = v.y; dst[2] = v.z; dst[3] = v.w;
        }
#pragma unroll
        for (int i = 0; i < 4; i++) {
            int idx = tid + i * 256;
            int row = idx >> 3;
            int k4  = (idx & 7) << 2;
            float4 v = *(const float4*)(Vw + (size_t)row * ENC_DIM + kc + k4);
            float* dst = &Bs[row * PITCH + k4];
            dst[0] = v.x; dst[1] = v.y; dst[2] = v.z; dst[3] = v.w;
        }
        __syncthreads();

#pragma unroll 4
        for (int p = 0; p < KC / 2; p++) {
            unsigned long long av[8], bv[8];
#pragma unroll
            for (int i = 0; i < 8; i++)
                av[i] = *(const unsigned long long*)&As[(ty * 8 + i) * PITCH + 2 * p];
#pragma unroll
            for (int j = 0; j < 8; j++)
                bv[j] = *(const unsigned long long*)&Bs[(tx + 16 * j) * PITCH + 2 * p];
#pragma unroll
            for (int i = 0; i < 8; i++)
#pragma unroll
                for (int j = 0; j < 8; j++)
                    asm("fma.rn.f32x2 %0, %1, %2, %0;"
                        : "+l"(acc[i][j]) : "l"(av[i]), "l"(bv[j]));
        }
    }

    // epilogue: score[t] = sum_c tanh(k[t,c] + Vb[c] + q[b,c]) * w[c] + wb
    float w_bias = wb[0];
#pragma unroll
    for (int i = 0; i < 8; i++) {
        float partial = 0.f;
#pragma unroll
        for (int j = 0; j < 8; j++) {
            int c = tx + 16 * j;
            float lo = __uint_as_float((unsigned)(acc[i][j] & 0xffffffffull));
            float hi = __uint_as_float((unsigned)(acc[i][j] >> 32));
            float kv = lo + hi;
            float v  = kv + sVb[c] + sq[c];
            partial += tanhf(v) * sw[c];
        }
        // reduce over the 16 tx lanes (xor masks stay within 16-lane half-warp)
#pragma unroll
        for (int off = 8; off; off >>= 1)
            partial += __shfl_xor_sync(0xffffffffu, partial, off);
        if (tx == 0)
            g_scores[b * TT + t0 + ty * 8 + i] = partial + w_bias;
    }
}

// ---------------- kernel 3: masked softmax per batch row ----------------
__global__ void softmax_kernel(const unsigned char* __restrict__ mask,
                               float* __restrict__ out_w) {
    int b   = blockIdx.x;
    int tid = threadIdx.x;          // 256 threads
    int lane = tid & 31, wid = tid >> 5;
    bool u8 = (g_mask_u8 != 0);
    __shared__ float redm[8];
    __shared__ float reds[8];
    __shared__ float bc[2];

    float vals[8];
    float mx = -CUDART_INF_F;
#pragma unroll
    for (int i = 0; i < 8; i++) {
        int t = tid + i * 256;
        float s = g_scores[b * TT + t];
        unsigned char m = u8 ? mask[b * TT + t] : mask[4 * (size_t)(b * TT + t)];
        if (m) s = -CUDART_INF_F;
        vals[i] = s;
        mx = fmaxf(mx, s);
    }
#pragma unroll
    for (int off = 16; off; off >>= 1)
        mx = fmaxf(mx, __shfl_xor_sync(0xffffffffu, mx, off));
    if (lane == 0) redm[wid] = mx;
    __syncthreads();
    if (tid == 0) {
        float m = redm[0];
#pragma unroll
        for (int w = 1; w < 8; w++) m = fmaxf(m, redm[w]);
        bc[0] = m;
    }
    __syncthreads();
    mx = bc[0];

    float sum = 0.f;
#pragma unroll
    for (int i = 0; i < 8; i++) {
        vals[i] = __expf(vals[i] - mx);   // exp(-inf - mx) = 0
        sum += vals[i];
    }
#pragma unroll
    for (int off = 16; off; off >>= 1)
        sum += __shfl_xor_sync(0xffffffffu, sum, off);
    if (lane == 0) reds[wid] = sum;
    __syncthreads();
    if (tid == 0) {
        float s = 0.f;
#pragma unroll
        for (int w = 0; w < 8; w++) s += reds[w];
        bc[1] = 1.f / s;
    }
    __syncthreads();
    float inv = bc[1];
#pragma unroll
    for (int i = 0; i < 8; i++)
        out_w[b * TT + tid + i * 256] = vals[i] * inv;
}

// ---------------- kernel 4: context partials (t split 8-way) ----------------
__global__ void ctx_partial_kernel(const float* __restrict__ enc,
                                   const float* __restrict__ weights) {
    int seg = blockIdx.x;   // 0..7
    int b   = blockIdx.y;   // 0..63
    int tid = threadIdx.x;  // 128 threads, each owns 4 consecutive enc dims
    __shared__ float ws[256];
    int tbase = seg * 256;
    ws[tid]       = weights[b * TT + tbase + tid];
    ws[tid + 128] = weights[b * TT + tbase + 128 + tid];
    __syncthreads();

    float4 acc = make_float4(0.f, 0.f, 0.f, 0.f);
    const float4* ep = (const float4*)(enc + ((size_t)b * TT + tbase) * ENC_DIM) + tid;
#pragma unroll 8
    for (int t = 0; t < 256; t++) {
        float4 v = ep[(size_t)t * (ENC_DIM / 4)];
        float w  = ws[t];
        acc.x += v.x * w; acc.y += v.y * w; acc.z += v.z * w; acc.w += v.w * w;
    }
    ((float4*)g_ctx_part)[((size_t)seg * BB + b) * (ENC_DIM / 4) + tid] = acc;
}

__global__ void ctx_combine_kernel(float* __restrict__ out_ctx) {
    int i = blockIdx.x * blockDim.x + threadIdx.x;   // B*ENC = 32768
    int b = i >> 9, e = i & 511;
    float s = 0.f;
#pragma unroll
    for (int seg = 0; seg < 8; seg++) s += g_ctx_part[seg][b][e];
    out_ctx[i] = s;
}

// ---------------- launch ----------------
extern "C" void kernel_launch(void* const* d_in, const int* in_sizes, int n_in,
                              void* d_out, int out_size) {
    const float*         enc  = (const float*)d_in[0];
    const float*         dec  = (const float*)d_in[1];
    const unsigned char* mask = (const unsigned char*)d_in[2];
    const float*         Vw   = (const float*)d_in[3];
    const float*         Vb   = (const float*)d_in[4];
    const float*         Ww   = (const float*)d_in[5];
    const float*         ww   = (const float*)d_in[6];
    const float*         wb   = (const float*)d_in[7];

    float* out_ctx = (float*)d_out;                    // [B, ENC_DIM]
    float* out_w   = (float*)d_out + BB * ENC_DIM;     // [B, T]

    detect_mask_kernel<<<1, 1024>>>((const uint4*)mask);
    q_kernel<<<BB, HID>>>(dec, Ww);
    scores_kernel<<<1024, 256>>>(enc, Vw, Vb, ww, wb);
    softmax_kernel<<<BB, 256>>>(mask, out_w);
    ctx_partial_kernel<<<dim3(8, BB), 128>>>(enc, out_w);
    ctx_combine_kernel<<<(BB * ENC_DIM) / 256, 256>>>(out_ctx);
}

// round 2
// speedup vs baseline: 1.0004x; 1.0004x over previous
#include <cuda_runtime.h>
#include <cstdint>
#include <math_constants.h>

#define ENC_DIM 512
#define DEC_DIM 1024
#define HID     128
#define BB      64
#define TT      2048

// ---------------- scratch (no cudaMalloc allowed) ----------------
__device__ float g_q[BB * HID];
__device__ float g_scores[BB * TT];
__device__ float g_ctx_part[8][BB][ENC_DIM];
__device__ int   g_mask_u8;

// ---------------- kernel 0: detect mask dtype ----------------
// mask is logically bool [B,T]. It may be stored as uint8 (1 byte/elem) or
// int32 (4 bytes/elem, values 0/1). Read the first B*T bytes (in-bounds under
// BOTH layouts) as u32 words: if storage is int32, every word is 0 or 1.
// If storage is uint8, words pack 4 bools -> some word > 1 with prob ~1.
__global__ void detect_mask_kernel(const uint4* __restrict__ m) {
    __shared__ int s;
    if (threadIdx.x == 0) s = 0;
    __syncthreads();
    int found = 0;
    const int n16 = (BB * TT) / 16;  // 8192 uint4 covering B*T bytes
    for (int i = threadIdx.x; i < n16; i += blockDim.x) {
        uint4 v = m[i];
        found |= (v.x > 1u) | (v.y > 1u) | (v.z > 1u) | (v.w > 1u);
    }
    if (found) atomicOr(&s, 1);
    __syncthreads();
    if (threadIdx.x == 0) g_mask_u8 = s;
}

// ---------------- kernel 1: q = decoder_state @ W_w^T  [B, HID] ----------------
__global__ void q_kernel(const float* __restrict__ dec, const float* __restrict__ Ww) {
    __shared__ float sdec[DEC_DIM];
    int b = blockIdx.x;
    for (int i = threadIdx.x; i < DEC_DIM; i += blockDim.x)
        sdec[i] = dec[b * DEC_DIM + i];
    __syncthreads();
    int h = threadIdx.x;  // 128 threads
    const float4* wr = (const float4*)(Ww + (size_t)h * DEC_DIM);
    const float4* dr = (const float4*)sdec;
    float acc = 0.f;
#pragma unroll 8
    for (int i = 0; i < DEC_DIM / 4; i++) {
        float4 w4 = wr[i];
        float4 d4 = dr[i];
        acc += w4.x * d4.x + w4.y * d4.y + w4.z * d4.z + w4.w * d4.w;
    }
    g_q[b * HID + h] = acc;
}

// ---------------- kernel 2: scores (the big GEMM + tanh epilogue) ----------------
// Tile: 128 tokens x 128 hid, K-chunks of 32. 256 threads = 16x16, each thread
// owns 8 rows (contiguous) x 8 cols (stride-16). Accumulation uses packed
// fma.rn.f32x2: each 64-bit acc holds (even-k partial, odd-k partial), pairs of
// adjacent k loaded directly as LDS.64 from smem (pitch 34 keeps 8B alignment
// and makes the strided-column B reads conflict-free).
#define KC    32
#define PITCH 34

__global__ __launch_bounds__(256, 1) void scores_kernel(
    const float* __restrict__ enc, const float* __restrict__ Vw,
    const float* __restrict__ Vb, const float* __restrict__ ww,
    const float* __restrict__ wb)
{
    __shared__ float As[128 * PITCH];
    __shared__ float Bs[128 * PITCH];
    __shared__ float sVb[HID], sq[HID], sw[HID];

    int bidx = blockIdx.x;         // 0..1023
    int b    = bidx >> 4;          // batch
    int t0   = (bidx & 15) << 7;   // token tile start

    int tid = threadIdx.x;
    int tx  = tid & 15;
    int ty  = tid >> 4;

    if (tid < HID) {
        sVb[tid] = Vb[tid];
        sq[tid]  = g_q[b * HID + tid];
        sw[tid]  = ww[tid];
    }

    const float* Ag = enc + ((size_t)(b * TT + t0)) * ENC_DIM;

    unsigned long long acc[8][8];
#pragma unroll
    for (int i = 0; i < 8; i++)
#pragma unroll
        for (int j = 0; j < 8; j++) acc[i][j] = 0ull;

    for (int kc = 0; kc < ENC_DIM; kc += KC) {
        __syncthreads();  // previous chunk fully consumed
        // load A tile: 128 rows x 32 cols (8 float4 per row), coalesced
#pragma unroll
        for (int i = 0; i < 4; i++) {
            int idx = tid + i * 256;       // 0..1023
            int row = idx >> 3;
            int k4  = (idx & 7) << 2;
            float4 v = *(const float4*)(Ag + (size_t)row * ENC_DIM + kc + k4);
            float* dst = &As[row * PITCH + k4];
            dst[0] = v.x; dst[1] = v.y; dst[2] = v.z; dst[3] = v.w;
        }
#pragma unroll
        for (int i = 0; i < 4; i++) {
            int idx = tid + i * 256;
            int row = idx >> 3;
            int k4  = (idx & 7) << 2;
            float4 v = *(const float4*)(Vw + (size_t)row * ENC_DIM + kc + k4);
            float* dst = &Bs[row * PITCH + k4];
            dst[0] = v.x; dst[1] = v.y; dst[2] = v.z; dst[3] = v.w;
        }
        __syncthreads();

#pragma unroll 4
        for (int p = 0; p < KC / 2; p++) {
            unsigned long long av[8], bv[8];
#pragma unroll
            for (int i = 0; i < 8; i++)
                av[i] = *(const unsigned long long*)&As[(ty * 8 + i) * PITCH + 2 * p];
#pragma unroll
            for (int j = 0; j < 8; j++)
                bv[j] = *(const unsigned long long*)&Bs[(tx + 16 * j) * PITCH + 2 * p];
#pragma unroll
            for (int i = 0; i < 8; i++)
#pragma unroll
                for (int j = 0; j < 8; j++)
                    asm("fma.rn.f32x2 %0, %1, %2, %0;"
                        : "+l"(acc[i][j]) : "l"(av[i]), "l"(bv[j]));
        }
    }

    // epilogue: score[t] = sum_c tanh(k[t,c] + Vb[c] + q[b,c]) * w[c] + wb
    float w_bias = wb[0];
#pragma unroll
    for (int i = 0; i < 8; i++) {
        float partial = 0.f;
#pragma unroll
        for (int j = 0; j < 8; j++) {
            int c = tx + 16 * j;
            float lo = __uint_as_float((unsigned)(acc[i][j] & 0xffffffffull));
            float hi = __uint_as_float((unsigned)(acc[i][j] >> 32));
            float kv = lo + hi;
            float v  = kv + sVb[c] + sq[c];
            partial += tanhf(v) * sw[c];
        }
        // reduce over the 16 tx lanes (xor masks stay within 16-lane half-warp)
#pragma unroll
        for (int off = 8; off; off >>= 1)
            partial += __shfl_xor_sync(0xffffffffu, partial, off);
        if (tx == 0)
            g_scores[b * TT + t0 + ty * 8 + i] = partial + w_bias;
    }
}

// ---------------- kernel 3: masked softmax per batch row ----------------
__global__ void softmax_kernel(const unsigned char* __restrict__ mask,
                               float* __restrict__ out_w) {
    int b   = blockIdx.x;
    int tid = threadIdx.x;          // 256 threads
    int lane = tid & 31, wid = tid >> 5;
    bool u8 = (g_mask_u8 != 0);
    __shared__ float redm[8];
    __shared__ float reds[8];
    __shared__ float bc[2];

    float vals[8];
    float mx = -CUDART_INF_F;
#pragma unroll
    for (int i = 0; i < 8; i++) {
        int t = tid + i * 256;
        float s = g_scores[b * TT + t];
        unsigned char m = u8 ? mask[b * TT + t] : mask[4 * (size_t)(b * TT + t)];
        if (m) s = -CUDART_INF_F;
        vals[i] = s;
        mx = fmaxf(mx, s);
    }
#pragma unroll
    for (int off = 16; off; off >>= 1)
        mx = fmaxf(mx, __shfl_xor_sync(0xffffffffu, mx, off));
    if (lane == 0) redm[wid] = mx;
    __syncthreads();
    if (tid == 0) {
        float m = redm[0];
#pragma unroll
        for (int w = 1; w < 8; w++) m = fmaxf(m, redm[w]);
        bc[0] = m;
    }
    __syncthreads();
    mx = bc[0];

    float sum = 0.f;
#pragma unroll
    for (int i = 0; i < 8; i++) {
        vals[i] = __expf(vals[i] - mx);   // exp(-inf - mx) = 0
        sum += vals[i];
    }
#pragma unroll
    for (int off = 16; off; off >>= 1)
        sum += __shfl_xor_sync(0xffffffffu, sum, off);
    if (lane == 0) reds[wid] = sum;
    __syncthreads();
    if (tid == 0) {
        float s = 0.f;
#pragma unroll
        for (int w = 0; w < 8; w++) s += reds[w];
        bc[1] = 1.f / s;
    }
    __syncthreads();
    float inv = bc[1];
#pragma unroll
    for (int i = 0; i < 8; i++)
        out_w[b * TT + tid + i * 256] = vals[i] * inv;
}

// ---------------- kernel 4: context partials (t split 8-way) ----------------
__global__ void ctx_partial_kernel(const float* __restrict__ enc,
                                   const float* __restrict__ weights) {
    int seg = blockIdx.x;   // 0..7
    int b   = blockIdx.y;   // 0..63
    int tid = threadIdx.x;  // 128 threads, each owns 4 consecutive enc dims
    __shared__ float ws[256];
    int tbase = seg * 256;
    ws[tid]       = weights[b * TT + tbase + tid];
    ws[tid + 128] = weights[b * TT + tbase + 128 + tid];
    __syncthreads();

    float4 acc = make_float4(0.f, 0.f, 0.f, 0.f);
    const float4* ep = (const float4*)(enc + ((size_t)b * TT + tbase) * ENC_DIM) + tid;
#pragma unroll 8
    for (int t = 0; t < 256; t++) {
        float4 v = ep[(size_t)t * (ENC_DIM / 4)];
        float w  = ws[t];
        acc.x += v.x * w; acc.y += v.y * w; acc.z += v.z * w; acc.w += v.w * w;
    }
    ((float4*)g_ctx_part)[((size_t)seg * BB + b) * (ENC_DIM / 4) + tid] = acc;
}

__global__ void ctx_combine_kernel(float* __restrict__ out_ctx) {
    int i = blockIdx.x * blockDim.x + threadIdx.x;   // B*ENC = 32768
    int b = i >> 9, e = i & 511;
    float s = 0.f;
#pragma unroll
    for (int seg = 0; seg < 8; seg++) s += g_ctx_part[seg][b][e];
    out_ctx[i] = s;
}

// ---------------- launch ----------------
extern "C" void kernel_launch(void* const* d_in, const int* in_sizes, int n_in,
                              void* d_out, int out_size) {
    const float*         enc  = (const float*)d_in[0];
    const float*         dec  = (const float*)d_in[1];
    const unsigned char* mask = (const unsigned char*)d_in[2];
    const float*         Vw   = (const float*)d_in[3];
    const float*         Vb   = (const float*)d_in[4];
    const float*         Ww   = (const float*)d_in[5];
    const float*         ww   = (const float*)d_in[6];
    const float*         wb   = (const float*)d_in[7];

    float* out_ctx = (float*)d_out;                    // [B, ENC_DIM]
    float* out_w   = (float*)d_out + BB * ENC_DIM;     // [B, T]

    detect_mask_kernel<<<1, 1024>>>((const uint4*)mask);
    q_kernel<<<BB, HID>>>(dec, Ww);
    scores_kernel<<<1024, 256>>>(enc, Vw, Vb, ww, wb);
    softmax_kernel<<<BB, 256>>>(mask, out_w);
    ctx_partial_kernel<<<dim3(8, BB), 128>>>(enc, out_w);
    ctx_combine_kernel<<<(BB * ENC_DIM) / 256, 256>>>(out_ctx);
}

// round 3
// speedup vs baseline: 2.3271x; 2.3262x over previous
#include <cuda_runtime.h>
#include <cstdint>
#include <math_constants.h>

#define ENC_DIM 512
#define DEC_DIM 1024
#define HID     128
#define BB      64
#define TT      2048

// ---------------- scratch (no cudaMalloc allowed) ----------------
__device__ float g_q[BB * HID];
__device__ float g_scores[BB * TT];
__device__ float g_ctx_part[16][BB][ENC_DIM];
__device__ int   g_mask_u8;

// ---------------- kernel 0: detect mask dtype ----------------
__global__ void detect_mask_kernel(const uint4* __restrict__ m) {
    __shared__ int s;
    if (threadIdx.x == 0) s = 0;
    __syncthreads();
    int found = 0;
    const int n16 = (BB * TT) / 16;
    for (int i = threadIdx.x; i < n16; i += blockDim.x) {
        uint4 v = m[i];
        found |= (v.x > 1u) | (v.y > 1u) | (v.z > 1u) | (v.w > 1u);
    }
    if (found) atomicOr(&s, 1);
    __syncthreads();
    if (threadIdx.x == 0) g_mask_u8 = s;
}

// ---------------- kernel 1: q = decoder_state @ W_w^T ----------------
__global__ void q_kernel(const float* __restrict__ dec, const float* __restrict__ Ww) {
    __shared__ float sdec[DEC_DIM];
    int b = blockIdx.x;
    for (int i = threadIdx.x; i < DEC_DIM; i += blockDim.x)
        sdec[i] = dec[b * DEC_DIM + i];
    __syncthreads();
    int h = threadIdx.x;
    const float4* wr = (const float4*)(Ww + (size_t)h * DEC_DIM);
    const float4* dr = (const float4*)sdec;
    float acc = 0.f;
#pragma unroll 8
    for (int i = 0; i < DEC_DIM / 4; i++) {
        float4 w4 = wr[i];
        float4 d4 = dr[i];
        acc += w4.x * d4.x + w4.y * d4.y + w4.z * d4.z + w4.w * d4.w;
    }
    g_q[b * HID + h] = acc;
}

// ---------------- kernel 2: scores via tf32 tensor-core MMA ----------------
// Block tile 128 tokens x 128 hid, KC=32. 8 warps in 4(M) x 2(N):
// warp tile 32x64 = 2 m16-tiles x 8 n8-tiles per k8 step.
// Inputs rounded to tf32 (cvt.rna) at smem-store time.
#define KC      32
#define PITCH_A 36

__device__ __forceinline__ unsigned f2tf32(float x) {
    unsigned r;
    asm("cvt.rna.tf32.f32 %0, %1;" : "=r"(r) : "f"(x));
    return r;
}

__global__ __launch_bounds__(256, 2) void scores_kernel(
    const float* __restrict__ enc, const float* __restrict__ Vw,
    const float* __restrict__ Vb, const float* __restrict__ ww,
    const float* __restrict__ wb)
{
    __shared__ unsigned As[128 * PITCH_A];   // [token][k]
    __shared__ unsigned Bs[128 * PITCH_A];   // [hid][k]
    __shared__ float sVb[HID], sq[HID], sw[HID];
    __shared__ float srow[128];

    int bidx = blockIdx.x;         // 0..1023
    int b    = bidx >> 4;
    int t0   = (bidx & 15) << 7;

    int tid    = threadIdx.x;
    int lane   = tid & 31;
    int wid    = tid >> 5;
    int warp_m = wid >> 1;         // 0..3
    int warp_n = wid & 1;          // 0..1
    int g      = lane >> 2;        // groupID 0..7
    int tig    = lane & 3;         // 0..3

    if (tid < HID) {
        sVb[tid]  = Vb[tid];
        sq[tid]   = g_q[b * HID + tid];
        sw[tid]   = ww[tid];
        srow[tid] = 0.f;
    }

    const float* Ag = enc + ((size_t)(b * TT + t0)) * ENC_DIM;

    float c[2][8][4];
#pragma unroll
    for (int mt = 0; mt < 2; mt++)
#pragma unroll
        for (int nt = 0; nt < 8; nt++)
#pragma unroll
            for (int r = 0; r < 4; r++) c[mt][nt][r] = 0.f;

    for (int kc = 0; kc < ENC_DIM; kc += KC) {
        __syncthreads();
#pragma unroll
        for (int i = 0; i < 4; i++) {
            int idx = tid + i * 256;          // 0..1023
            int row = idx >> 3;
            int k4  = (idx & 7) << 2;
            float4 v = *(const float4*)(Ag + (size_t)row * ENC_DIM + kc + k4);
            unsigned* dst = &As[row * PITCH_A + k4];
            dst[0] = f2tf32(v.x); dst[1] = f2tf32(v.y);
            dst[2] = f2tf32(v.z); dst[3] = f2tf32(v.w);
        }
#pragma unroll
        for (int i = 0; i < 4; i++) {
            int idx = tid + i * 256;
            int row = idx >> 3;
            int k4  = (idx & 7) << 2;
            float4 v = *(const float4*)(Vw + (size_t)row * ENC_DIM + kc + k4);
            unsigned* dst = &Bs[row * PITCH_A + k4];
            dst[0] = f2tf32(v.x); dst[1] = f2tf32(v.y);
            dst[2] = f2tf32(v.z); dst[3] = f2tf32(v.w);
        }
        __syncthreads();

#pragma unroll
        for (int ks = 0; ks < KC / 8; ks++) {
            int k0 = ks * 8;
            // A fragments: 2 m16 tiles
            unsigned a[2][4];
#pragma unroll
            for (int mt = 0; mt < 2; mt++) {
                int r0 = warp_m * 32 + mt * 16 + g;
                a[mt][0] = As[r0 * PITCH_A + k0 + tig];
                a[mt][1] = As[(r0 + 8) * PITCH_A + k0 + tig];
                a[mt][2] = As[r0 * PITCH_A + k0 + tig + 4];
                a[mt][3] = As[(r0 + 8) * PITCH_A + k0 + tig + 4];
            }
#pragma unroll
            for (int nt = 0; nt < 8; nt++) {
                int n0 = warp_n * 64 + nt * 8;
                unsigned b0 = Bs[(n0 + g) * PITCH_A + k0 + tig];
                unsigned b1 = Bs[(n0 + g) * PITCH_A + k0 + tig + 4];
#pragma unroll
                for (int mt = 0; mt < 2; mt++) {
                    asm volatile(
                        "mma.sync.aligned.m16n8k8.row.col.f32.tf32.tf32.f32 "
                        "{%0,%1,%2,%3}, {%4,%5,%6,%7}, {%8,%9}, {%0,%1,%2,%3};"
                        : "+f"(c[mt][nt][0]), "+f"(c[mt][nt][1]),
                          "+f"(c[mt][nt][2]), "+f"(c[mt][nt][3])
                        : "r"(a[mt][0]), "r"(a[mt][1]), "r"(a[mt][2]), "r"(a[mt][3]),
                          "r"(b0), "r"(b1));
                }
            }
        }
    }
    __syncthreads();

    // epilogue: score[t] = sum_c tanh(k + Vb + q) * w   (+wb later)
#pragma unroll
    for (int mt = 0; mt < 2; mt++) {
#pragma unroll
        for (int rr = 0; rr < 2; rr++) {
            int row = warp_m * 32 + mt * 16 + rr * 8 + g;
            float partial = 0.f;
#pragma unroll
            for (int nt = 0; nt < 8; nt++) {
                int c0 = warp_n * 64 + nt * 8 + 2 * tig;
                float v0 = c[mt][nt][2 * rr]     + sVb[c0]     + sq[c0];
                float v1 = c[mt][nt][2 * rr + 1] + sVb[c0 + 1] + sq[c0 + 1];
                partial += tanhf(v0) * sw[c0] + tanhf(v1) * sw[c0 + 1];
            }
            partial += __shfl_xor_sync(0xffffffffu, partial, 1);
            partial += __shfl_xor_sync(0xffffffffu, partial, 2);
            if (tig == 0) atomicAdd(&srow[row], partial);
        }
    }
    __syncthreads();
    if (tid < 128)
        g_scores[b * TT + t0 + tid] = srow[tid] + wb[0];
}

// ---------------- kernel 3: masked softmax per batch row ----------------
__global__ void softmax_kernel(const unsigned char* __restrict__ mask,
                               float* __restrict__ out_w) {
    int b   = blockIdx.x;
    int tid = threadIdx.x;          // 256 threads
    int lane = tid & 31, wid = tid >> 5;
    bool u8 = (g_mask_u8 != 0);
    __shared__ float redm[8];
    __shared__ float reds[8];
    __shared__ float bc[2];

    float vals[8];
    float mx = -CUDART_INF_F;
#pragma unroll
    for (int i = 0; i < 8; i++) {
        int t = tid + i * 256;
        float s = g_scores[b * TT + t];
        unsigned char m = u8 ? mask[b * TT + t] : mask[4 * (size_t)(b * TT + t)];
        if (m) s = -CUDART_INF_F;
        vals[i] = s;
        mx = fmaxf(mx, s);
    }
#pragma unroll
    for (int off = 16; off; off >>= 1)
        mx = fmaxf(mx, __shfl_xor_sync(0xffffffffu, mx, off));
    if (lane == 0) redm[wid] = mx;
    __syncthreads();
    if (tid == 0) {
        float m = redm[0];
#pragma unroll
        for (int w = 1; w < 8; w++) m = fmaxf(m, redm[w]);
        bc[0] = m;
    }
    __syncthreads();
    mx = bc[0];

    float sum = 0.f;
#pragma unroll
    for (int i = 0; i < 8; i++) {
        vals[i] = __expf(vals[i] - mx);
        sum += vals[i];
    }
#pragma unroll
    for (int off = 16; off; off >>= 1)
        sum += __shfl_xor_sync(0xffffffffu, sum, off);
    if (lane == 0) reds[wid] = sum;
    __syncthreads();
    if (tid == 0) {
        float s = 0.f;
#pragma unroll
        for (int w = 0; w < 8; w++) s += reds[w];
        bc[1] = 1.f / s;
    }
    __syncthreads();
    float inv = bc[1];
#pragma unroll
    for (int i = 0; i < 8; i++)
        out_w[b * TT + tid + i * 256] = vals[i] * inv;
}

// ---------------- kernel 4: context partials (t split 16-way) ----------------
__global__ void ctx_partial_kernel(const float* __restrict__ enc,
                                   const float* __restrict__ weights) {
    int seg = blockIdx.x;   // 0..15
    int b   = blockIdx.y;   // 0..63
    int tid = threadIdx.x;  // 128 threads, each owns 4 consecutive enc dims
    __shared__ float ws[128];
    int tbase = seg * 128;
    ws[tid] = weights[b * TT + tbase + tid];
    __syncthreads();

    float4 acc = make_float4(0.f, 0.f, 0.f, 0.f);
    const float4* ep = (const float4*)(enc + ((size_t)b * TT + tbase) * ENC_DIM) + tid;
#pragma unroll 8
    for (int t = 0; t < 128; t++) {
        float4 v = ep[(size_t)t * (ENC_DIM / 4)];
        float w  = ws[t];
        acc.x += v.x * w; acc.y += v.y * w; acc.z += v.z * w; acc.w += v.w * w;
    }
    ((float4*)g_ctx_part)[((size_t)seg * BB + b) * (ENC_DIM / 4) + tid] = acc;
}

__global__ void ctx_combine_kernel(float* __restrict__ out_ctx) {
    int i = blockIdx.x * blockDim.x + threadIdx.x;   // B*ENC = 32768
    int b = i >> 9, e = i & 511;
    float s = 0.f;
#pragma unroll
    for (int seg = 0; seg < 16; seg++) s += g_ctx_part[seg][b][e];
    out_ctx[i] = s;
}

// ---------------- launch ----------------
extern "C" void kernel_launch(void* const* d_in, const int* in_sizes, int n_in,
                              void* d_out, int out_size) {
    const float*         enc  = (const float*)d_in[0];
    const float*         dec  = (const float*)d_in[1];
    const unsigned char* mask = (const unsigned char*)d_in[2];
    const float*         Vw   = (const float*)d_in[3];
    const float*         Vb   = (const float*)d_in[4];
    const float*         Ww   = (const float*)d_in[5];
    const float*         ww   = (const float*)d_in[6];
    const float*         wb   = (const float*)d_in[7];

    float* out_ctx = (float*)d_out;                    // [B, ENC_DIM]
    float* out_w   = (float*)d_out + BB * ENC_DIM;     // [B, T]

    detect_mask_kernel<<<1, 1024>>>((const uint4*)mask);
    q_kernel<<<BB, HID>>>(dec, Ww);
    scores_kernel<<<1024, 256>>>(enc, Vw, Vb, ww, wb);
    softmax_kernel<<<BB, 256>>>(mask, out_w);
    ctx_partial_kernel<<<dim3(16, BB), 128>>>(enc, out_w);
    ctx_combine_kernel<<<(BB * ENC_DIM) / 256, 256>>>(out_ctx);
}